// round 11
// baseline (speedup 1.0000x reference)
#include <cuda_runtime.h>
#include <math.h>

#define I_SIZE 256
#define N_NEURONS 1024
#define N_DIMS 64
#define D_FEAT 128
#define T_STEPS 256   // = O_SIZE, only first 256 scan steps are observable
#define W_ELEMS (D_FEAT * D_FEAT)

// scratch: w_t for all 256 steps (128 KB) + progress counter
__device__ float g_w[T_STEPS * D_FEAT];
__device__ int g_done;   // monotonic within a replay; stale values across
                         // graph replays are value-safe (same inputs =>
                         // identical g_w contents)

// Fast tanh for the chain: (e^{2x}-1)/(e^{2x}+1), abs err ~1e-6 (feedback-safe).
__device__ __forceinline__ float ftanh(float x)
{
    float xc = fminf(fmaxf(x, -15.f), 15.f);
    float e  = __expf(2.f * xc);
    return __fdividef(e - 1.f, e + 1.f);
}

// MUFU tanh for the output layer only (no feedback; single instruction).
__device__ __forceinline__ float tanh_mufu(float x)
{
    float y;
    asm("tanh.approx.f32 %0, %1;" : "=f"(y) : "f"(x));
    return y;
}

// One chain step: w_t = v_t @ W_t with packed f32x2 FMAs, publish w_t
// (+flag on odd steps), update v_{t+1} = tanh(alpha_t * w_t).
__device__ __forceinline__ void chain_step(
    int t, const ulonglong2 (&cur)[8],
    float* sh_v, float* sh_part, const float* sh_alpha,
    int kg, int jq, int tid)
{
    // Two uniform-address (broadcast) LDS.128 instead of 8 scalar broadcasts.
    const float4 v01 = *(const float4*)&sh_v[kg * 8];
    const float4 v23 = *(const float4*)&sh_v[kg * 8 + 4];
    const float vk[8] = { v01.x, v01.y, v01.z, v01.w,
                          v23.x, v23.y, v23.z, v23.w };

    unsigned long long acc01 = 0ull, acc23 = 0ull;   // f32x2 {0,0} pairs
    #pragma unroll
    for (int r = 0; r < 8; r++) {
        unsigned long long vkp;
        const unsigned int vb = __float_as_uint(vk[r]);
        asm("mov.b64 %0, {%1, %1};" : "=l"(vkp) : "r"(vb));
        asm("fma.rn.f32x2 %0, %1, %2, %0;"
            : "+l"(acc01) : "l"(cur[r].x), "l"(vkp));
        asm("fma.rn.f32x2 %0, %1, %2, %0;"
            : "+l"(acc23) : "l"(cur[r].y), "l"(vkp));
    }
    // store packed accumulators straight to smem (16B-aligned)
    ulonglong2 st; st.x = acc01; st.y = acc23;
    *(ulonglong2*)&sh_part[kg * D_FEAT + 4 * jq] = st;
    __syncthreads();

    // 128 threads: tree-sum the 16 partials, publish w, update v.
    if (tid < D_FEAT) {
        float p[16];
        #pragma unroll
        for (int g = 0; g < 16; g++) p[g] = sh_part[g * D_FEAT + tid];
        const float s01 = (p[0] + p[1])  + (p[2] + p[3]);
        const float s23 = (p[4] + p[5])  + (p[6] + p[7]);
        const float s45 = (p[8] + p[9])  + (p[10] + p[11]);
        const float s67 = (p[12] + p[13]) + (p[14] + p[15]);
        const float s = (s01 + s23) + (s45 + s67);
        g_w[t * D_FEAT + tid] = s;
        sh_v[tid] = ftanh(sh_alpha[t] * s);
    }
    __syncthreads();   // CTA-scope HB: all g_w stores precede tid 0 below
    if ((t & 1) && tid == 0) {
        // gpu-scope release store every 2nd step; cumulativity over the
        // bar.sync makes both steps' g_w writes visible to acquirers.
        asm volatile("st.release.gpu.b32 [%0], %1;"
                     :: "l"(&g_done), "r"(t + 1) : "memory");
    }
}

__global__ __launch_bounds__(512, 1) void fused_kernel(
    const float* __restrict__ x, const float* __restrict__ pos_head,
    const float* __restrict__ pos_tail, const float* __restrict__ W,
    const float* __restrict__ a, float* __restrict__ out)
{
    const int tid = threadIdx.x;

    if (blockIdx.x == 0) {
        // ================= serial recurrence (1 CTA) =================
        __shared__ __align__(16) float sh_v[D_FEAT];
        __shared__ __align__(16) float sh_part[16 * D_FEAT];
        __shared__ __align__(16) float sh_alpha[T_STEPS];
        __shared__ __align__(16) float sh_T[N_DIMS];
        __shared__ float sh_s0;

        // --- one-time init ---
        if (tid < T_STEPS) {
            sh_alpha[tid] = a[(size_t)tid * N_NEURONS + tid + 1];
        }
        if (tid < N_DIMS) {
            float s = 0.f;
            #pragma unroll 4
            for (int k = 0; k < I_SIZE; k++) s += pos_tail[k * N_DIMS + tid];
            sh_T[tid] = s;
        }
        __syncthreads();
        if (tid < 32) {
            float p = sh_T[tid] * pos_head[tid] + sh_T[tid + 32] * pos_head[tid + 32];
            #pragma unroll
            for (int off = 16; off > 0; off >>= 1)
                p += __shfl_xor_sync(0xffffffffu, p, off);
            if (tid == 0) sh_s0 = p;
        }
        __syncthreads();
        if (tid < D_FEAT) {
            float u = 0.f;
            #pragma unroll 4
            for (int i = 0; i < I_SIZE; i++) u += x[i * D_FEAT + tid];
            sh_v[tid] = sh_s0 * u;
        }
        __syncthreads();

        const int jq = tid & 31;   // j quad: j = 4*jq .. 4*jq+3
        const int kg = tid >> 5;   // k group: rows kg*8 .. kg*8+7
        const float* Wbase = W + (size_t)(kg * 8) * D_FEAT + 4 * jq;

        // Register double-buffer: prefetch W (fp32, as packed u64 pairs) for
        // step t+1 while computing step t. W has 768 steps, so t+1/t+2
        // (<= 257) are always in-bounds -> branch-free prefetch.
        ulonglong2 bufA[8], bufB[8];
        #pragma unroll
        for (int r = 0; r < 8; r++)
            bufA[r] = *(const ulonglong2*)(Wbase + (size_t)r * D_FEAT);

        for (int t = 0; t < T_STEPS; t += 2) {
            const float* Wn1 = Wbase + (size_t)(t + 1) * W_ELEMS;
            #pragma unroll
            for (int r = 0; r < 8; r++)
                bufB[r] = *(const ulonglong2*)(Wn1 + (size_t)r * D_FEAT);
            chain_step(t, bufA, sh_v, sh_part, sh_alpha, kg, jq, tid);

            const float* Wn2 = Wbase + (size_t)(t + 2) * W_ELEMS;
            #pragma unroll
            for (int r = 0; r < 8; r++)
                bufA[r] = *(const ulonglong2*)(Wn2 + (size_t)r * D_FEAT);
            chain_step(t + 1, bufB, sh_v, sh_part, sh_alpha, kg, jq, tid);
        }
    } else {
        // ================= output expansion (2048 CTAs) =================
        // block handles (t, 128-row slab of l); waits only for w_t.
        const int bid = (int)blockIdx.x - 1;
        const int t  = bid >> 3;
        const int lb = (bid & 7) << 7;   // *128

        __shared__ __align__(16) float wsh[D_FEAT];

        if (tid == 0) {
            int d;
            do {
                asm volatile("ld.acquire.gpu.b32 %0, [%1];"
                             : "=r"(d) : "l"(&g_done) : "memory");
                if (d > t) break;
                __nanosleep(128);
            } while (true);
        }
        __syncthreads();   // acquire propagates via CTA barrier to all threads

        if (tid < D_FEAT) wsh[tid] = g_w[t * D_FEAT + tid];
        __syncthreads();

        const float* __restrict__ arow = a + (size_t)t * N_NEURONS + lb;
        float* __restrict__ obase = out + ((size_t)t * N_NEURONS + lb) * D_FEAT;

        #pragma unroll
        for (int it = 0; it < 8; it++) {
            const int item = it * 512 + tid;   // 0..4095 over (l_local, jq)
            const int ll = item >> 5;          // l within slab (warp-uniform)
            const int jq2 = item & 31;         // j quad (lane id)
            const float av = __ldcs(arow + ll);            // streaming read
            const float4 wv = *(const float4*)(&wsh[4 * jq2]);
            float4 o;
            o.x = tanh_mufu(av * wv.x);
            o.y = tanh_mufu(av * wv.y);
            o.z = tanh_mufu(av * wv.z);
            o.w = tanh_mufu(av * wv.w);
            __stcs((float4*)(obase + ll * D_FEAT + 4 * jq2), o);  // evict-first
        }
    }
}

extern "C" void kernel_launch(void* const* d_in, const int* in_sizes, int n_in,
                              void* d_out, int out_size)
{
    const float* x        = (const float*)d_in[0];   // (256, 128)
    const float* pos_head = (const float*)d_in[1];   // (1024, 64)
    const float* pos_tail = (const float*)d_in[2];   // (1024, 64)
    const float* W        = (const float*)d_in[3];   // (768, 128, 128)
    const float* a        = (const float*)d_in[4];   // (768, 1024)
    float* out            = (float*)d_out;           // (256, 1024, 128)

    fused_kernel<<<1 + T_STEPS * 8, 512>>>(x, pos_head, pos_tail, W, a, out);
}

// round 12
// speedup vs baseline: 1.1400x; 1.1400x over previous
#include <cuda_runtime.h>
#include <math.h>

#define I_SIZE 256
#define N_NEURONS 1024
#define N_DIMS 64
#define D_FEAT 128
#define T_STEPS 256   // = O_SIZE, only first 256 scan steps are observable
#define W_ELEMS (D_FEAT * D_FEAT)
#define SENT_U 0x7FC0DEADu   // specific quiet-NaN payload; no finite-math
                             // result in this net can produce it

// v_t stream: v_0 .. v_256 (v_256 written by CTA 255, never read).
// Data-as-flag: each float is its own readiness indicator; the init kernel
// re-poisons t>=1 at the start of every (graph-replayed) launch sequence.
__device__ float g_v[(T_STEPS + 1) * D_FEAT];

// Fast tanh for the chain: (e^{2x}-1)/(e^{2x}+1), abs err ~1e-6 (feedback-safe).
__device__ __forceinline__ float ftanh(float x)
{
    float xc = fminf(fmaxf(x, -15.f), 15.f);
    float e  = __expf(2.f * xc);
    return __fdividef(e - 1.f, e + 1.f);
}

// MUFU tanh for the output layer only (no feedback; single instruction).
__device__ __forceinline__ float tanh_mufu(float x)
{
    float y;
    asm("tanh.approx.f32 %0, %1;" : "=f"(y) : "f"(x));
    return y;
}

// ---------------------------------------------------------------------------
// Init kernel (runs before chain_kernel each replay, stream-ordered):
//   CTA 0      : computes v_0 = s0 * u  (s0 = (sum pos_tail[:256]) . pos_head[0],
//                u[j] = sum_i x[i,j]) and writes real values to g_v[0].
//   CTAs 1..64 : poison g_v[1..256] with the sentinel.
// ---------------------------------------------------------------------------
__global__ __launch_bounds__(512) void init_kernel(
    const float* __restrict__ x, const float* __restrict__ pos_head,
    const float* __restrict__ pos_tail)
{
    const int tid = threadIdx.x;

    if (blockIdx.x > 0) {
        const int idx = ((int)blockIdx.x - 1) * 512 + tid;   // 0..32767
        g_v[D_FEAT + idx] = __uint_as_float(SENT_U);
        return;
    }

    __shared__ float sh_T[N_DIMS];
    __shared__ float sh_p[4 * D_FEAT];
    __shared__ float sh_s0;

    if (tid < N_DIMS) {
        float s = 0.f;
        #pragma unroll 4
        for (int k = 0; k < I_SIZE; k++) s += pos_tail[k * N_DIMS + tid];
        sh_T[tid] = s;
    }
    __syncthreads();
    if (tid < 32) {
        float p = sh_T[tid] * pos_head[tid] + sh_T[tid + 32] * pos_head[tid + 32];
        #pragma unroll
        for (int off = 16; off > 0; off >>= 1)
            p += __shfl_xor_sync(0xffffffffu, p, off);
        if (tid == 0) sh_s0 = p;
    }
    // u partials: 4 groups of 128 threads, 64 rows each (coalesced)
    {
        const int g = tid >> 7, j = tid & (D_FEAT - 1);
        float u = 0.f;
        #pragma unroll 4
        for (int i = g * 64; i < g * 64 + 64; i++) u += x[i * D_FEAT + j];
        sh_p[g * D_FEAT + j] = u;
    }
    __syncthreads();
    if (tid < D_FEAT) {
        const float u = (sh_p[tid] + sh_p[D_FEAT + tid]) +
                        (sh_p[2 * D_FEAT + tid] + sh_p[3 * D_FEAT + tid]);
        g_v[tid] = sh_s0 * u;   // deterministic fixed-order sums
    }
}

// ---------------------------------------------------------------------------
// Chain kernel: CTA t owns step t.
//   1. preload W_t into registers (off critical path, parallel across CTAs)
//   2. poll own element of g_v[t] (data-as-flag, ld.relaxed.gpu)
//   3. w_t = v_t @ W_t  (regs + smem reduction)
//   4. publish v_{t+1} = ftanh(alpha_t * w_t) ASAP (st.relaxed.gpu)
//   5. expansion: out[t, l, j] = tanh(a[t,l] * w_t[j])  (512 KB, own tile)
// ---------------------------------------------------------------------------
__global__ __launch_bounds__(512, 1) void chain_kernel(
    const float* __restrict__ W, const float* __restrict__ a,
    float* __restrict__ out)
{
    const int t   = (int)blockIdx.x;
    const int tid = (int)threadIdx.x;
    const int jq  = tid & 31;   // j quad: j = 4*jq .. 4*jq+3
    const int kg  = tid >> 5;   // k group: rows kg*8 .. kg*8+7

    __shared__ __align__(16) float sh_v[D_FEAT];
    __shared__ __align__(16) float sh_part[16 * D_FEAT];
    __shared__ __align__(16) float sh_w[D_FEAT];
    __shared__ __align__(16) float sh_a[N_NEURONS];

    // 1. W_t -> registers (64 KB per CTA; all CTAs pull in parallel)
    float4 Wr[8];
    const float* Wb = W + (size_t)t * W_ELEMS + (size_t)(kg * 8) * D_FEAT + 4 * jq;
    #pragma unroll
    for (int r = 0; r < 8; r++)
        Wr[r] = *(const float4*)(Wb + (size_t)r * D_FEAT);

    const float alpha = a[(size_t)t * N_NEURONS + t + 1];

    // a-row for the expansion phase (4 KB)
    for (int i = tid; i < N_NEURONS; i += 512)
        sh_a[i] = __ldcs(a + (size_t)t * N_NEURONS + i);

    // 2. poll incoming v_t: each thread waits on its own element only
    if (tid < D_FEAT) {
        const float* src = &g_v[t * D_FEAT + tid];
        unsigned int u;
        do {
            asm volatile("ld.relaxed.gpu.b32 %0, [%1];" : "=r"(u) : "l"(src));
        } while (u == SENT_U);
        sh_v[tid] = __uint_as_float(u);
    }
    __syncthreads();

    // 3. w = v @ W_t
    const float4 v01 = *(const float4*)&sh_v[kg * 8];
    const float4 v23 = *(const float4*)&sh_v[kg * 8 + 4];
    const float vk[8] = { v01.x, v01.y, v01.z, v01.w,
                          v23.x, v23.y, v23.z, v23.w };
    float4 acc = make_float4(0.f, 0.f, 0.f, 0.f);
    #pragma unroll
    for (int r = 0; r < 8; r++) {
        acc.x = fmaf(vk[r], Wr[r].x, acc.x);
        acc.y = fmaf(vk[r], Wr[r].y, acc.y);
        acc.z = fmaf(vk[r], Wr[r].z, acc.z);
        acc.w = fmaf(vk[r], Wr[r].w, acc.w);
    }
    *(float4*)&sh_part[kg * D_FEAT + 4 * jq] = acc;
    __syncthreads();

    // 4. reduce + publish v_{t+1} (critical path ends at the STG)
    if (tid < D_FEAT) {
        float p[16];
        #pragma unroll
        for (int g = 0; g < 16; g++) p[g] = sh_part[g * D_FEAT + tid];
        const float s01 = (p[0] + p[1])   + (p[2] + p[3]);
        const float s23 = (p[4] + p[5])   + (p[6] + p[7]);
        const float s45 = (p[8] + p[9])   + (p[10] + p[11]);
        const float s67 = (p[12] + p[13]) + (p[14] + p[15]);
        const float s = (s01 + s23) + (s45 + s67);
        const float vn = ftanh(alpha * s);
        asm volatile("st.relaxed.gpu.b32 [%0], %1;"
                     :: "l"(&g_v[(t + 1) * D_FEAT + tid]),
                        "r"(__float_as_uint(vn)) : "memory");
        sh_w[tid] = s;
    }
    __syncthreads();

    // 5. expansion: out[t, l, j] = tanh(a[t,l] * w[j]); 512 KB streaming
    float* __restrict__ obase = out + (size_t)t * N_NEURONS * D_FEAT;
    #pragma unroll 4
    for (int it = 0; it < 64; it++) {
        const int item = it * 512 + tid;   // 0..32767 over (l, jq)
        const int ll = item >> 5;          // l (warp-uniform)
        const int q  = item & 31;          // j quad (lane id)
        const float av = sh_a[ll];
        const float4 wv = *(const float4*)&sh_w[4 * q];
        float4 o;
        o.x = tanh_mufu(av * wv.x);
        o.y = tanh_mufu(av * wv.y);
        o.z = tanh_mufu(av * wv.z);
        o.w = tanh_mufu(av * wv.w);
        __stcs((float4*)(obase + (size_t)ll * D_FEAT + 4 * q), o);
    }
}

extern "C" void kernel_launch(void* const* d_in, const int* in_sizes, int n_in,
                              void* d_out, int out_size)
{
    const float* x        = (const float*)d_in[0];   // (256, 128)
    const float* pos_head = (const float*)d_in[1];   // (1024, 64)
    const float* pos_tail = (const float*)d_in[2];   // (1024, 64)
    const float* W        = (const float*)d_in[3];   // (768, 128, 128)
    const float* a        = (const float*)d_in[4];   // (768, 1024)
    float* out            = (float*)d_out;           // (256, 1024, 128)

    init_kernel<<<65, 512>>>(x, pos_head, pos_tail);
    chain_kernel<<<T_STEPS, 512>>>(W, a, out);
}

// round 13
// speedup vs baseline: 1.3370x; 1.1728x over previous
#include <cuda_runtime.h>
#include <math.h>

#define I_SIZE 256
#define N_NEURONS 1024
#define N_DIMS 64
#define D_FEAT 128
#define T_STEPS 256   // = O_SIZE, only first 256 scan steps are observable
#define W_ELEMS (D_FEAT * D_FEAT)
#define STEPS_PER_CTA 2
#define N_CHAIN_CTAS (T_STEPS / STEPS_PER_CTA)
#define SENT_U 0x7FC0DEADu   // specific quiet-NaN payload; no finite-math
                             // result in this net can produce it

// v_t stream (only even t slots are used for global handoff; odd-step v
// stays in the owning CTA's smem). Data-as-flag: each float is its own
// readiness indicator; init_kernel re-poisons t>=1 every replay.
__device__ float g_v[(T_STEPS + 1) * D_FEAT];

// Fast tanh for the chain: (e^{2x}-1)/(e^{2x}+1), abs err ~1e-6 (feedback-safe).
__device__ __forceinline__ float ftanh(float x)
{
    float xc = fminf(fmaxf(x, -15.f), 15.f);
    float e  = __expf(2.f * xc);
    return __fdividef(e - 1.f, e + 1.f);
}

// MUFU tanh for the output layer only (no feedback; single instruction).
__device__ __forceinline__ float tanh_mufu(float x)
{
    float y;
    asm("tanh.approx.f32 %0, %1;" : "=f"(y) : "f"(x));
    return y;
}

// ---------------------------------------------------------------------------
// Init kernel (stream-ordered before chain_kernel each replay):
//   CTA 0      : v_0 = s0 * u   (s0 = (sum pos_tail[:256]) . pos_head[0],
//                u[j] = sum_i x[i,j]) -> g_v[0]
//   CTAs 1..64 : poison g_v[1..256] with the sentinel.
// ---------------------------------------------------------------------------
__global__ __launch_bounds__(512) void init_kernel(
    const float* __restrict__ x, const float* __restrict__ pos_head,
    const float* __restrict__ pos_tail)
{
    const int tid = threadIdx.x;

    if (blockIdx.x > 0) {
        const int idx = ((int)blockIdx.x - 1) * 512 + tid;   // 0..32767
        g_v[D_FEAT + idx] = __uint_as_float(SENT_U);
        return;
    }

    __shared__ float sh_T[N_DIMS];
    __shared__ float sh_p[4 * D_FEAT];
    __shared__ float sh_s0;

    if (tid < N_DIMS) {
        float s = 0.f;
        #pragma unroll 4
        for (int k = 0; k < I_SIZE; k++) s += pos_tail[k * N_DIMS + tid];
        sh_T[tid] = s;
    }
    __syncthreads();
    if (tid < 32) {
        float p = sh_T[tid] * pos_head[tid] + sh_T[tid + 32] * pos_head[tid + 32];
        #pragma unroll
        for (int off = 16; off > 0; off >>= 1)
            p += __shfl_xor_sync(0xffffffffu, p, off);
        if (tid == 0) sh_s0 = p;
    }
    {
        const int g = tid >> 7, j = tid & (D_FEAT - 1);
        float u = 0.f;
        #pragma unroll 4
        for (int i = g * 64; i < g * 64 + 64; i++) u += x[i * D_FEAT + j];
        sh_p[g * D_FEAT + j] = u;
    }
    __syncthreads();
    if (tid < D_FEAT) {
        const float u = (sh_p[tid] + sh_p[D_FEAT + tid]) +
                        (sh_p[2 * D_FEAT + tid] + sh_p[3 * D_FEAT + tid]);
        g_v[tid] = sh_s0 * u;   // deterministic fixed-order sums
    }
}

// matvec partial: acc over this thread's 8 k-rows, into sh_part
__device__ __forceinline__ void matvec_partial(
    const float4 (&Wr)[8], const float* sh_v, float* sh_part, int kg, int jq)
{
    const float4 v01 = *(const float4*)&sh_v[kg * 8];
    const float4 v23 = *(const float4*)&sh_v[kg * 8 + 4];
    const float vk[8] = { v01.x, v01.y, v01.z, v01.w,
                          v23.x, v23.y, v23.z, v23.w };
    float4 acc = make_float4(0.f, 0.f, 0.f, 0.f);
    #pragma unroll
    for (int r = 0; r < 8; r++) {
        acc.x = fmaf(vk[r], Wr[r].x, acc.x);
        acc.y = fmaf(vk[r], Wr[r].y, acc.y);
        acc.z = fmaf(vk[r], Wr[r].z, acc.z);
        acc.w = fmaf(vk[r], Wr[r].w, acc.w);
    }
    *(float4*)&sh_part[kg * D_FEAT + 4 * jq] = acc;
}

// tree-sum the 16 partials for column tid (<128)
__device__ __forceinline__ float reduce16(const float* sh_part, int tid)
{
    float p[16];
    #pragma unroll
    for (int g = 0; g < 16; g++) p[g] = sh_part[g * D_FEAT + tid];
    const float s01 = (p[0] + p[1])   + (p[2] + p[3]);
    const float s23 = (p[4] + p[5])   + (p[6] + p[7]);
    const float s45 = (p[8] + p[9])   + (p[10] + p[11]);
    const float s67 = (p[12] + p[13]) + (p[14] + p[15]);
    return (s01 + s23) + (s45 + s67);
}

// ---------------------------------------------------------------------------
// Chain kernel: CTA i owns steps t0=2i and t1=2i+1.
//   1. preload W_t0, W_t1 into registers (parallel across CTAs, off path)
//   2. poll g_v[t0] (data-as-flag, one element per thread)
//   3. step A in smem; step B; publish v_{t0+2} via st.relaxed.gpu
//   4. expansion for both tiles (1 MB, streaming, off critical path)
// ---------------------------------------------------------------------------
__global__ __launch_bounds__(512, 1) void chain_kernel(
    const float* __restrict__ W, const float* __restrict__ a,
    float* __restrict__ out)
{
    const int bid = (int)blockIdx.x;       // 0..127
    const int t0  = bid * STEPS_PER_CTA;
    const int t1  = t0 + 1;
    const int tid = (int)threadIdx.x;
    const int jq  = tid & 31;   // j quad: j = 4*jq .. 4*jq+3
    const int kg  = tid >> 5;   // k group: rows kg*8 .. kg*8+7

    __shared__ __align__(16) float sh_v[D_FEAT];
    __shared__ __align__(16) float sh_part[16 * D_FEAT];
    __shared__ __align__(16) float sh_w[2][D_FEAT];
    __shared__ __align__(16) float sh_a[2][N_NEURONS];

    // 1. W for both steps -> registers (128 KB per CTA, parallel pull)
    float4 WrA[8], WrB[8];
    {
        const float* WbA = W + (size_t)t0 * W_ELEMS + (size_t)(kg * 8) * D_FEAT + 4 * jq;
        const float* WbB = WbA + W_ELEMS;
        #pragma unroll
        for (int r = 0; r < 8; r++) {
            WrA[r] = *(const float4*)(WbA + (size_t)r * D_FEAT);
            WrB[r] = *(const float4*)(WbB + (size_t)r * D_FEAT);
        }
    }
    const float alpha0 = a[(size_t)t0 * N_NEURONS + t0 + 1];
    const float alpha1 = a[(size_t)t1 * N_NEURONS + t1 + 1];

    // a-rows for the expansion phase (8 KB)
    for (int i = tid; i < N_NEURONS; i += 512) {
        sh_a[0][i] = __ldcs(a + (size_t)t0 * N_NEURONS + i);
        sh_a[1][i] = __ldcs(a + (size_t)t1 * N_NEURONS + i);
    }

    // 2. poll incoming v_{t0}: each thread waits on its own element only
    if (tid < D_FEAT) {
        const float* src = &g_v[t0 * D_FEAT + tid];
        unsigned int u;
        do {
            asm volatile("ld.relaxed.gpu.b32 %0, [%1];" : "=r"(u) : "l"(src));
        } while (u == SENT_U);
        sh_v[tid] = __uint_as_float(u);
    }
    __syncthreads();

    // 3a. step A (global v -> smem v)
    matvec_partial(WrA, sh_v, sh_part, kg, jq);
    __syncthreads();
    if (tid < D_FEAT) {
        const float s = reduce16(sh_part, tid);
        sh_w[0][tid] = s;
        sh_v[tid] = ftanh(alpha0 * s);
    }
    __syncthreads();

    // 3b. step B (smem v -> publish)
    matvec_partial(WrB, sh_v, sh_part, kg, jq);
    __syncthreads();
    if (tid < D_FEAT) {
        const float s = reduce16(sh_part, tid);
        sh_w[1][tid] = s;
        const float vn = ftanh(alpha1 * s);
        asm volatile("st.relaxed.gpu.b32 [%0], %1;"
                     :: "l"(&g_v[(t0 + 2) * D_FEAT + tid]),
                        "r"(__float_as_uint(vn)) : "memory");
    }
    __syncthreads();

    // 4. expansion for both steps: out[t, l, j] = tanh(a[t,l] * w_t[j])
    #pragma unroll
    for (int s = 0; s < 2; s++) {
        float* __restrict__ obase = out + (size_t)(t0 + s) * N_NEURONS * D_FEAT;
        const float* __restrict__ arow = sh_a[s];
        const float* __restrict__ wrow = sh_w[s];
        #pragma unroll 4
        for (int it = 0; it < 64; it++) {
            const int item = it * 512 + tid;   // 0..32767 over (l, jq)
            const int ll = item >> 5;          // l (warp-uniform)
            const int q  = item & 31;          // j quad (lane id)
            const float av = arow[ll];
            const float4 wv = *(const float4*)&wrow[4 * q];
            float4 o;
            o.x = tanh_mufu(av * wv.x);
            o.y = tanh_mufu(av * wv.y);
            o.z = tanh_mufu(av * wv.z);
            o.w = tanh_mufu(av * wv.w);
            __stcs((float4*)(obase + (size_t)ll * D_FEAT + 4 * q), o);
        }
    }
}

extern "C" void kernel_launch(void* const* d_in, const int* in_sizes, int n_in,
                              void* d_out, int out_size)
{
    const float* x        = (const float*)d_in[0];   // (256, 128)
    const float* pos_head = (const float*)d_in[1];   // (1024, 64)
    const float* pos_tail = (const float*)d_in[2];   // (1024, 64)
    const float* W        = (const float*)d_in[3];   // (768, 128, 128)
    const float* a        = (const float*)d_in[4];   // (768, 1024)
    float* out            = (float*)d_out;           // (256, 1024, 128)

    init_kernel<<<65, 512>>>(x, pos_head, pos_tail);
    chain_kernel<<<N_CHAIN_CTAS, 512>>>(W, a, out);
}

// round 14
// speedup vs baseline: 1.5553x; 1.1633x over previous
#include <cuda_runtime.h>
#include <math.h>

#define I_SIZE 256
#define N_NEURONS 1024
#define N_DIMS 64
#define D_FEAT 128
#define T_STEPS 256   // = O_SIZE, only first 256 scan steps are observable
#define W_ELEMS (D_FEAT * D_FEAT)
#define STEPS_PER_CTA 2
#define N_CHAIN_CTAS (T_STEPS / STEPS_PER_CTA)   // 128
#define CLUSTER_N 4                               // CTAs per cluster (8 steps)
#define SENT_U 0x7FC0DEADu   // specific quiet-NaN payload; no finite-math
                             // result in this net can produce it

// Global v handoff slots (used only at cluster boundaries). Data-as-flag:
// each float is its own readiness indicator; init_kernel re-poisons every
// replay.
__device__ float g_v[(T_STEPS + 1) * D_FEAT];

// Fast tanh for the chain: (e^{2x}-1)/(e^{2x}+1), abs err ~1e-6 (feedback-safe).
__device__ __forceinline__ float ftanh(float x)
{
    float xc = fminf(fmaxf(x, -15.f), 15.f);
    float e  = __expf(2.f * xc);
    return __fdividef(e - 1.f, e + 1.f);
}

// MUFU tanh for the output layer only (no feedback; single instruction).
__device__ __forceinline__ float tanh_mufu(float x)
{
    float y;
    asm("tanh.approx.f32 %0, %1;" : "=f"(y) : "f"(x));
    return y;
}

__device__ __forceinline__ unsigned int smem_u32(const void* p)
{
    unsigned int a;
    asm("{ .reg .u64 t; cvta.to.shared.u64 t, %1; cvt.u32.u64 %0, t; }"
        : "=r"(a) : "l"(p));
    return a;
}

// ---------------------------------------------------------------------------
// Init kernel (stream-ordered before chain_kernel each replay):
//   CTA 0      : v_0 = s0 * u -> g_v[0]
//   CTAs 1..64 : poison g_v[1..256] with the sentinel.
// ---------------------------------------------------------------------------
__global__ __launch_bounds__(512) void init_kernel(
    const float* __restrict__ x, const float* __restrict__ pos_head,
    const float* __restrict__ pos_tail)
{
    const int tid = threadIdx.x;

    if (blockIdx.x > 0) {
        const int idx = ((int)blockIdx.x - 1) * 512 + tid;   // 0..32767
        g_v[D_FEAT + idx] = __uint_as_float(SENT_U);
        return;
    }

    __shared__ float sh_T[N_DIMS];
    __shared__ float sh_p[4 * D_FEAT];
    __shared__ float sh_s0;

    if (tid < N_DIMS) {
        float s = 0.f;
        #pragma unroll 4
        for (int k = 0; k < I_SIZE; k++) s += pos_tail[k * N_DIMS + tid];
        sh_T[tid] = s;
    }
    __syncthreads();
    if (tid < 32) {
        float p = sh_T[tid] * pos_head[tid] + sh_T[tid + 32] * pos_head[tid + 32];
        #pragma unroll
        for (int off = 16; off > 0; off >>= 1)
            p += __shfl_xor_sync(0xffffffffu, p, off);
        if (tid == 0) sh_s0 = p;
    }
    {
        const int g = tid >> 7, j = tid & (D_FEAT - 1);
        float u = 0.f;
        #pragma unroll 4
        for (int i = g * 64; i < g * 64 + 64; i++) u += x[i * D_FEAT + j];
        sh_p[g * D_FEAT + j] = u;
    }
    __syncthreads();
    if (tid < D_FEAT) {
        const float u = (sh_p[tid] + sh_p[D_FEAT + tid]) +
                        (sh_p[2 * D_FEAT + tid] + sh_p[3 * D_FEAT + tid]);
        g_v[tid] = sh_s0 * u;   // deterministic fixed-order sums
    }
}

// matvec partial: acc over this thread's 8 k-rows, into sh_part
__device__ __forceinline__ void matvec_partial(
    const float4 (&Wr)[8], const float* sh_v, float* sh_part, int kg, int jq)
{
    const float4 v01 = *(const float4*)&sh_v[kg * 8];
    const float4 v23 = *(const float4*)&sh_v[kg * 8 + 4];
    const float vk[8] = { v01.x, v01.y, v01.z, v01.w,
                          v23.x, v23.y, v23.z, v23.w };
    float4 acc = make_float4(0.f, 0.f, 0.f, 0.f);
    #pragma unroll
    for (int r = 0; r < 8; r++) {
        acc.x = fmaf(vk[r], Wr[r].x, acc.x);
        acc.y = fmaf(vk[r], Wr[r].y, acc.y);
        acc.z = fmaf(vk[r], Wr[r].z, acc.z);
        acc.w = fmaf(vk[r], Wr[r].w, acc.w);
    }
    *(float4*)&sh_part[kg * D_FEAT + 4 * jq] = acc;
}

// tree-sum the 16 partials for column tid (<128)
__device__ __forceinline__ float reduce16(const float* sh_part, int tid)
{
    float p[16];
    #pragma unroll
    for (int g = 0; g < 16; g++) p[g] = sh_part[g * D_FEAT + tid];
    const float s01 = (p[0] + p[1])   + (p[2] + p[3]);
    const float s23 = (p[4] + p[5])   + (p[6] + p[7]);
    const float s45 = (p[8] + p[9])   + (p[10] + p[11]);
    const float s67 = (p[12] + p[13]) + (p[14] + p[15]);
    return (s01 + s23) + (s45 + s67);
}

// ---------------------------------------------------------------------------
// Chain kernel, clustered. CTA bid owns steps 2*bid, 2*bid+1. Cluster of 4
// CTAs = 8 consecutive steps; intra-cluster v handoff goes through DSMEM
// (remote smem store + local LDS poll), only cluster boundaries touch L2.
// ---------------------------------------------------------------------------
__global__ __launch_bounds__(512, 1) __cluster_dims__(CLUSTER_N, 1, 1)
void chain_kernel(const float* __restrict__ W, const float* __restrict__ a,
                  float* __restrict__ out)
{
    const int bid = (int)blockIdx.x;       // 0..127
    const int t0  = bid * STEPS_PER_CTA;
    const int t1  = t0 + 1;
    const int tid = (int)threadIdx.x;
    const int jq  = tid & 31;   // j quad: j = 4*jq .. 4*jq+3
    const int kg  = tid >> 5;   // k group: rows kg*8 .. kg*8+7

    unsigned int rank;
    asm("mov.u32 %0, %%cluster_ctarank;" : "=r"(rank));

    __shared__ __align__(16) float sh_vin[D_FEAT];   // DSMEM inbox
    __shared__ __align__(16) float sh_v[D_FEAT];
    __shared__ __align__(16) float sh_part[16 * D_FEAT];
    __shared__ __align__(16) float sh_w[2][D_FEAT];
    __shared__ __align__(16) float sh_a[2][N_NEURONS];

    // Poison own inbox BEFORE any peer can write (peers write only after
    // receiving their own v, which is gated behind this cluster barrier).
    if (tid < D_FEAT) sh_vin[tid] = __uint_as_float(SENT_U);

    // 1. W for both steps -> registers (128 KB per CTA, parallel pull)
    float4 WrA[8], WrB[8];
    {
        const float* WbA = W + (size_t)t0 * W_ELEMS + (size_t)(kg * 8) * D_FEAT + 4 * jq;
        const float* WbB = WbA + W_ELEMS;
        #pragma unroll
        for (int r = 0; r < 8; r++) {
            WrA[r] = *(const float4*)(WbA + (size_t)r * D_FEAT);
            WrB[r] = *(const float4*)(WbB + (size_t)r * D_FEAT);
        }
    }
    const float alpha0 = a[(size_t)t0 * N_NEURONS + t0 + 1];
    const float alpha1 = a[(size_t)t1 * N_NEURONS + t1 + 1];

    // a-rows for the expansion phase (8 KB)
    for (int i = tid; i < N_NEURONS; i += 512) {
        sh_a[0][i] = __ldcs(a + (size_t)t0 * N_NEURONS + i);
        sh_a[1][i] = __ldcs(a + (size_t)t1 * N_NEURONS + i);
    }

    // Inbox poisoning must be cluster-visible before peers may write.
    asm volatile("barrier.cluster.arrive.aligned;" ::: "memory");
    asm volatile("barrier.cluster.wait.aligned;" ::: "memory");

    // 2. receive v_{t0}
    if (tid < D_FEAT) {
        if (rank == 0) {
            // cluster head: poll global slot (L2)
            const float* src = &g_v[t0 * D_FEAT + tid];
            unsigned int u;
            do {
                asm volatile("ld.relaxed.gpu.b32 %0, [%1];" : "=r"(u) : "l"(src));
            } while (u == SENT_U);
            sh_v[tid] = __uint_as_float(u);
        } else {
            // poll own DSMEM inbox (local LDS, fast detect)
            const unsigned int addr = smem_u32(&sh_vin[tid]);
            unsigned int u;
            do {
                asm volatile("ld.relaxed.cluster.shared::cta.b32 %0, [%1];"
                             : "=r"(u) : "r"(addr));
            } while (u == SENT_U);
            sh_v[tid] = __uint_as_float(u);
        }
    }
    __syncthreads();

    // 3a. step A (incoming v -> smem v)
    matvec_partial(WrA, sh_v, sh_part, kg, jq);
    __syncthreads();
    if (tid < D_FEAT) {
        const float s = reduce16(sh_part, tid);
        sh_w[0][tid] = s;
        sh_v[tid] = ftanh(alpha0 * s);
    }
    __syncthreads();

    // 3b. step B (smem v -> publish)
    matvec_partial(WrB, sh_v, sh_part, kg, jq);
    __syncthreads();
    if (tid < D_FEAT) {
        const float s = reduce16(sh_part, tid);
        sh_w[1][tid] = s;
        const float vn = ftanh(alpha1 * s);
        if (rank < CLUSTER_N - 1) {
            // DSMEM handoff to next CTA's inbox (data-as-flag)
            const unsigned int laddr = smem_u32(&sh_vin[tid]);
            asm volatile(
                "{ .reg .b32 ra; mapa.shared::cluster.u32 ra, %0, %1;\n\t"
                "  st.relaxed.cluster.shared::cluster.b32 [ra], %2; }"
                :: "r"(laddr), "r"(rank + 1), "r"(__float_as_uint(vn))
                : "memory");
        } else {
            // cluster boundary: publish through L2 to next cluster's head
            asm volatile("st.relaxed.gpu.b32 [%0], %1;"
                         :: "l"(&g_v[(t0 + 2) * D_FEAT + tid]),
                            "r"(__float_as_uint(vn)) : "memory");
        }
    }
    __syncthreads();

    // 4. expansion for both steps: out[t, l, j] = tanh(a[t,l] * w_t[j])
    #pragma unroll
    for (int s = 0; s < 2; s++) {
        float* __restrict__ obase = out + (size_t)(t0 + s) * N_NEURONS * D_FEAT;
        const float* __restrict__ arow = sh_a[s];
        const float* __restrict__ wrow = sh_w[s];
        #pragma unroll 4
        for (int it = 0; it < 64; it++) {
            const int item = it * 512 + tid;   // 0..32767 over (l, jq)
            const int ll = item >> 5;          // l (warp-uniform)
            const int q  = item & 31;          // j quad (lane id)
            const float av = arow[ll];
            const float4 wv = *(const float4*)&wrow[4 * q];
            float4 o;
            o.x = tanh_mufu(av * wv.x);
            o.y = tanh_mufu(av * wv.y);
            o.z = tanh_mufu(av * wv.z);
            o.w = tanh_mufu(av * wv.w);
            __stcs((float4*)(obase + (size_t)ll * D_FEAT + 4 * q), o);
        }
    }
}

extern "C" void kernel_launch(void* const* d_in, const int* in_sizes, int n_in,
                              void* d_out, int out_size)
{
    const float* x        = (const float*)d_in[0];   // (256, 128)
    const float* pos_head = (const float*)d_in[1];   // (1024, 64)
    const float* pos_tail = (const float*)d_in[2];   // (1024, 64)
    const float* W        = (const float*)d_in[3];   // (768, 128, 128)
    const float* a        = (const float*)d_in[4];   // (768, 1024)
    float* out            = (float*)d_out;           // (256, 1024, 128)

    init_kernel<<<65, 512>>>(x, pos_head, pos_tail);
    chain_kernel<<<N_CHAIN_CTAS, 512>>>(W, a, out);
}

// round 15
// speedup vs baseline: 1.5815x; 1.0169x over previous
#include <cuda_runtime.h>
#include <math.h>

#define I_SIZE 256
#define N_NEURONS 1024
#define N_DIMS 64
#define D_FEAT 128
#define T_STEPS 256   // = O_SIZE, only first 256 scan steps are observable
#define W_ELEMS (D_FEAT * D_FEAT)
#define STEPS_PER_CTA 2
#define N_CHAIN_CTAS (T_STEPS / STEPS_PER_CTA)   // 128
#define CLUSTER_N 8                               // CTAs per cluster (16 steps)
#define SENT_U 0x7FC0DEADu   // specific quiet-NaN payload; no finite-math
                             // result in this net can produce it

// Global v handoff slots (used only at cluster boundaries). Data-as-flag:
// each float is its own readiness indicator; init_kernel re-poisons every
// replay.
__device__ float g_v[(T_STEPS + 1) * D_FEAT];

// Fast tanh for the chain: (e^{2x}-1)/(e^{2x}+1), abs err ~1e-6 (feedback-safe).
__device__ __forceinline__ float ftanh(float x)
{
    float xc = fminf(fmaxf(x, -15.f), 15.f);
    float e  = __expf(2.f * xc);
    return __fdividef(e - 1.f, e + 1.f);
}

// MUFU tanh for the output layer only (no feedback; single instruction).
__device__ __forceinline__ float tanh_mufu(float x)
{
    float y;
    asm("tanh.approx.f32 %0, %1;" : "=f"(y) : "f"(x));
    return y;
}

__device__ __forceinline__ unsigned int smem_u32(const void* p)
{
    unsigned int a;
    asm("{ .reg .u64 t; cvta.to.shared.u64 t, %1; cvt.u32.u64 %0, t; }"
        : "=r"(a) : "l"(p));
    return a;
}

// ---------------------------------------------------------------------------
// Init kernel (stream-ordered before chain_kernel each replay):
//   CTA 0      : v_0 = s0 * u -> g_v[0]
//   CTAs 1..64 : poison g_v[1..256] with the sentinel.
// ---------------------------------------------------------------------------
__global__ __launch_bounds__(512) void init_kernel(
    const float* __restrict__ x, const float* __restrict__ pos_head,
    const float* __restrict__ pos_tail)
{
    const int tid = threadIdx.x;

    if (blockIdx.x > 0) {
        const int idx = ((int)blockIdx.x - 1) * 512 + tid;   // 0..32767
        g_v[D_FEAT + idx] = __uint_as_float(SENT_U);
        return;
    }

    __shared__ float sh_T[N_DIMS];
    __shared__ float sh_p[4 * D_FEAT];
    __shared__ float sh_s0;

    if (tid < N_DIMS) {
        float s = 0.f;
        #pragma unroll 4
        for (int k = 0; k < I_SIZE; k++) s += pos_tail[k * N_DIMS + tid];
        sh_T[tid] = s;
    }
    __syncthreads();
    if (tid < 32) {
        float p = sh_T[tid] * pos_head[tid] + sh_T[tid + 32] * pos_head[tid + 32];
        #pragma unroll
        for (int off = 16; off > 0; off >>= 1)
            p += __shfl_xor_sync(0xffffffffu, p, off);
        if (tid == 0) sh_s0 = p;
    }
    {
        const int g = tid >> 7, j = tid & (D_FEAT - 1);
        float u = 0.f;
        #pragma unroll 4
        for (int i = g * 64; i < g * 64 + 64; i++) u += x[i * D_FEAT + j];
        sh_p[g * D_FEAT + j] = u;
    }
    __syncthreads();
    if (tid < D_FEAT) {
        const float u = (sh_p[tid] + sh_p[D_FEAT + tid]) +
                        (sh_p[2 * D_FEAT + tid] + sh_p[3 * D_FEAT + tid]);
        g_v[tid] = sh_s0 * u;   // deterministic fixed-order sums
    }
}

// matvec partial: acc over this thread's 8 k-rows, into sh_part
__device__ __forceinline__ void matvec_partial(
    const float4 (&Wr)[8], const float* sh_v, float* sh_part, int kg, int jq)
{
    const float4 v01 = *(const float4*)&sh_v[kg * 8];
    const float4 v23 = *(const float4*)&sh_v[kg * 8 + 4];
    const float vk[8] = { v01.x, v01.y, v01.z, v01.w,
                          v23.x, v23.y, v23.z, v23.w };
    float4 acc = make_float4(0.f, 0.f, 0.f, 0.f);
    #pragma unroll
    for (int r = 0; r < 8; r++) {
        acc.x = fmaf(vk[r], Wr[r].x, acc.x);
        acc.y = fmaf(vk[r], Wr[r].y, acc.y);
        acc.z = fmaf(vk[r], Wr[r].z, acc.z);
        acc.w = fmaf(vk[r], Wr[r].w, acc.w);
    }
    *(float4*)&sh_part[kg * D_FEAT + 4 * jq] = acc;
}

// tree-sum the 16 partials for column tid (<128)
__device__ __forceinline__ float reduce16(const float* sh_part, int tid)
{
    float p[16];
    #pragma unroll
    for (int g = 0; g < 16; g++) p[g] = sh_part[g * D_FEAT + tid];
    const float s01 = (p[0] + p[1])   + (p[2] + p[3]);
    const float s23 = (p[4] + p[5])   + (p[6] + p[7]);
    const float s45 = (p[8] + p[9])   + (p[10] + p[11]);
    const float s67 = (p[12] + p[13]) + (p[14] + p[15]);
    return (s01 + s23) + (s45 + s67);
}

// ---------------------------------------------------------------------------
// Chain kernel, clustered. CTA bid owns steps 2*bid, 2*bid+1. Cluster of 8
// CTAs = 16 consecutive steps; intra-cluster v handoff goes through DSMEM
// (remote cluster store + LOCAL volatile-LDS poll), only cluster boundaries
// touch L2.
// ---------------------------------------------------------------------------
__global__ __launch_bounds__(512, 1) __cluster_dims__(CLUSTER_N, 1, 1)
void chain_kernel(const float* __restrict__ W, const float* __restrict__ a,
                  float* __restrict__ out)
{
    const int bid = (int)blockIdx.x;       // 0..127
    const int t0  = bid * STEPS_PER_CTA;
    const int t1  = t0 + 1;
    const int tid = (int)threadIdx.x;
    const int jq  = tid & 31;   // j quad: j = 4*jq .. 4*jq+3
    const int kg  = tid >> 5;   // k group: rows kg*8 .. kg*8+7

    unsigned int rank;
    asm("mov.u32 %0, %%cluster_ctarank;" : "=r"(rank));

    __shared__ __align__(16) float sh_vin[D_FEAT];   // DSMEM inbox
    __shared__ __align__(16) float sh_v[D_FEAT];
    __shared__ __align__(16) float sh_part[16 * D_FEAT];
    __shared__ __align__(16) float sh_w[2][D_FEAT];
    __shared__ __align__(16) float sh_a[2][N_NEURONS];

    // Poison own inbox BEFORE any peer can write (peers write only after
    // receiving their own v, which is gated behind the cluster barrier).
    if (tid < D_FEAT) sh_vin[tid] = __uint_as_float(SENT_U);

    // 1. W for both steps -> registers (128 KB per CTA, parallel pull)
    float4 WrA[8], WrB[8];
    {
        const float* WbA = W + (size_t)t0 * W_ELEMS + (size_t)(kg * 8) * D_FEAT + 4 * jq;
        const float* WbB = WbA + W_ELEMS;
        #pragma unroll
        for (int r = 0; r < 8; r++) {
            WrA[r] = *(const float4*)(WbA + (size_t)r * D_FEAT);
            WrB[r] = *(const float4*)(WbB + (size_t)r * D_FEAT);
        }
    }
    const float alpha0 = a[(size_t)t0 * N_NEURONS + t0 + 1];
    const float alpha1 = a[(size_t)t1 * N_NEURONS + t1 + 1];

    // a-rows for the expansion phase (8 KB)
    for (int i = tid; i < N_NEURONS; i += 512) {
        sh_a[0][i] = __ldcs(a + (size_t)t0 * N_NEURONS + i);
        sh_a[1][i] = __ldcs(a + (size_t)t1 * N_NEURONS + i);
    }

    // Inbox poisoning must be cluster-visible before peers may write.
    asm volatile("barrier.cluster.arrive.aligned;" ::: "memory");
    asm volatile("barrier.cluster.wait.aligned;" ::: "memory");

    // 2. receive v_{t0}
    if (tid < D_FEAT) {
        if (rank == 0) {
            // cluster head: poll global slot (L2)
            const float* src = &g_v[t0 * D_FEAT + tid];
            unsigned int u;
            do {
                asm volatile("ld.relaxed.gpu.b32 %0, [%1];" : "=r"(u) : "l"(src));
            } while (u == SENT_U);
            sh_v[tid] = __uint_as_float(u);
        } else {
            // poll own inbox with a cheap LOCAL volatile LDS (smem is
            // uncached; the remote cluster store lands in this same smem,
            // and a 29-cyc LDS observes it — no cluster-scope load needed)
            const unsigned int addr = smem_u32(&sh_vin[tid]);
            unsigned int u;
            do {
                asm volatile("ld.volatile.shared.b32 %0, [%1];"
                             : "=r"(u) : "r"(addr));
            } while (u == SENT_U);
            sh_v[tid] = __uint_as_float(u);
        }
    }
    __syncthreads();

    // 3a. step A (incoming v -> smem v)
    matvec_partial(WrA, sh_v, sh_part, kg, jq);
    __syncthreads();
    if (tid < D_FEAT) {
        const float s = reduce16(sh_part, tid);
        sh_w[0][tid] = s;
        sh_v[tid] = ftanh(alpha0 * s);
    }
    __syncthreads();

    // 3b. step B (smem v -> publish)
    matvec_partial(WrB, sh_v, sh_part, kg, jq);
    __syncthreads();
    if (tid < D_FEAT) {
        const float s = reduce16(sh_part, tid);
        sh_w[1][tid] = s;
        const float vn = ftanh(alpha1 * s);
        if (rank < CLUSTER_N - 1) {
            // DSMEM handoff to next CTA's inbox (data-as-flag)
            const unsigned int laddr = smem_u32(&sh_vin[tid]);
            asm volatile(
                "{ .reg .b32 ra; mapa.shared::cluster.u32 ra, %0, %1;\n\t"
                "  st.relaxed.cluster.shared::cluster.b32 [ra], %2; }"
                :: "r"(laddr), "r"(rank + 1), "r"(__float_as_uint(vn))
                : "memory");
        } else {
            // cluster boundary: publish through L2 to next cluster's head
            asm volatile("st.relaxed.gpu.b32 [%0], %1;"
                         :: "l"(&g_v[(t0 + 2) * D_FEAT + tid]),
                            "r"(__float_as_uint(vn)) : "memory");
        }
    }
    __syncthreads();

    // 4. expansion for both steps: out[t, l, j] = tanh(a[t,l] * w_t[j])
    #pragma unroll
    for (int s = 0; s < 2; s++) {
        float* __restrict__ obase = out + (size_t)(t0 + s) * N_NEURONS * D_FEAT;
        const float* __restrict__ arow = sh_a[s];
        const float* __restrict__ wrow = sh_w[s];
        #pragma unroll 4
        for (int it = 0; it < 64; it++) {
            const int item = it * 512 + tid;   // 0..32767 over (l, jq)
            const int ll = item >> 5;          // l (warp-uniform)
            const int q  = item & 31;          // j quad (lane id)
            const float av = arow[ll];
            const float4 wv = *(const float4*)&wrow[4 * q];
            float4 o;
            o.x = tanh_mufu(av * wv.x);
            o.y = tanh_mufu(av * wv.y);
            o.z = tanh_mufu(av * wv.z);
            o.w = tanh_mufu(av * wv.w);
            __stcs((float4*)(obase + (size_t)ll * D_FEAT + 4 * q), o);
        }
    }
}

extern "C" void kernel_launch(void* const* d_in, const int* in_sizes, int n_in,
                              void* d_out, int out_size)
{
    const float* x        = (const float*)d_in[0];   // (256, 128)
    const float* pos_head = (const float*)d_in[1];   // (1024, 64)
    const float* pos_tail = (const float*)d_in[2];   // (1024, 64)
    const float* W        = (const float*)d_in[3];   // (768, 128, 128)
    const float* a        = (const float*)d_in[4];   // (768, 1024)
    float* out            = (float*)d_out;           // (256, 1024, 128)

    init_kernel<<<65, 512>>>(x, pos_head, pos_tail);
    chain_kernel<<<N_CHAIN_CTAS, 512>>>(W, a, out);
}